// round 4
// baseline (speedup 1.0000x reference)
#include <cuda_runtime.h>

// CAM: out[b] = (q[b] @ k[b]^T) @ v[b] + v[b]
// Reassociated: S[b] = k[b]^T @ v[b] (49x49); out[b] = q[b] @ S[b] + v[b]
// B=128, C=1024, N=49 (padded to 56 for packed f32x2 math).
//
// 3 kernels:
//   A: grid (128,8)  partial S over 128-ch slices -> SP_glob (padded 49x56)
//   R: grid (128)    reduce 8 partials -> S_red
//   B: grid (128,8)  out-slice = q_slice @ S + v_slice   (f32x2 packed FMA)

#define BB 128
#define CC 1024
#define NN 49
#define NPAD 56
#define SSZ (NN * NPAD)     // 2744
#define PP 8
#define CH 128
#define SC 64

__device__ float SP_glob[BB * PP * SSZ];   // 11.2 MB partial-S scratch
__device__ float S_red[BB * SSZ];          // 1.4 MB reduced S

typedef unsigned long long u64;

__device__ __forceinline__ u64 pack2(float lo, float hi) {
    u64 r; asm("mov.b64 %0, {%1,%2};" : "=l"(r) : "f"(lo), "f"(hi)); return r;
}
__device__ __forceinline__ void unpack2(u64 p, float& lo, float& hi) {
    asm("mov.b64 {%0,%1}, %2;" : "=f"(lo), "=f"(hi) : "l"(p));
}
__device__ __forceinline__ u64 fma2(u64 a, u64 b, u64 c) {
    u64 d; asm("fma.rn.f32x2 %0, %1, %2, %3;" : "=l"(d) : "l"(a), "l"(b), "l"(c));
    return d;
}

// ---------------- Kernel A: partial S = k_slice^T @ v_slice ----------------
__global__ __launch_bounds__(256)
void cam_partS(const float* __restrict__ k, const float* __restrict__ v) {
    __shared__ __align__(16) float k_sh[SC * NN];     // 12.25 KB (stride 49)
    __shared__ __align__(16) float v_sh[SC * NPAD];   // 14.0 KB  (stride 56, zero-padded)
    __shared__ __align__(16) float S_sh[SSZ];         // 10.7 KB

    const int b = blockIdx.x;
    const int p = blockIdx.y;
    const int tid = threadIdx.x;
    const size_t base = ((size_t)b * CC + (size_t)p * CH) * NN;
    const float* kb = k + base;
    const float* vb = v + base;

    for (int idx = tid; idx < SSZ; idx += 256) S_sh[idx] = 0.f;

    // 4 groups x 49 threads; thread tile = 7 S-rows x 8 S-cols (packed x4).
    const int g  = tid / 49;            // active when g < 4
    const int t  = tid % 49;
    const int ti = (t / 7) * 7;         // row base (k index)
    const int tj = (t % 7) * 8;         // col base in padded cols (v index)

    u64 acc[7][4];
    #pragma unroll
    for (int a = 0; a < 7; a++)
        #pragma unroll
        for (int d = 0; d < 4; d++) acc[a][d] = 0ULL;

    #pragma unroll
    for (int chunk = 0; chunk < CH / SC; chunk++) {
        __syncthreads();
        // stage k: linear float4 copy (784 vec loads)
        const float4* k4 = (const float4*)(kb + (size_t)chunk * SC * NN);
        for (int idx = tid; idx < (SC * NN) / 4; idx += 256)
            ((float4*)k_sh)[idx] = k4[idx];
        // stage v: scalar copy into padded layout, zero-fill cols 49..55
        const float* vsrc = vb + (size_t)chunk * SC * NN;
        for (int idx = tid; idx < SC * NPAD; idx += 256) {
            int cc = idx / NPAD, ii = idx % NPAD;
            v_sh[idx] = (ii < NN) ? vsrc[cc * NN + ii] : 0.f;
        }
        __syncthreads();

        if (g < 4) {
            #pragma unroll 4
            for (int cl = 0; cl < 16; cl++) {
                const int cc = g * 16 + cl;
                u64 krp[7], vp[4];
                #pragma unroll
                for (int a = 0; a < 7; a++) {
                    float kv = k_sh[cc * NN + ti + a];
                    krp[a] = pack2(kv, kv);
                }
                #pragma unroll
                for (int d = 0; d < 4; d++)
                    vp[d] = *(const u64*)&v_sh[cc * NPAD + tj + 2 * d];
                #pragma unroll
                for (int a = 0; a < 7; a++)
                    #pragma unroll
                    for (int d = 0; d < 4; d++)
                        acc[a][d] = fma2(krp[a], vp[d], acc[a][d]);
            }
        }
    }

    if (g < 4) {
        #pragma unroll
        for (int a = 0; a < 7; a++)
            #pragma unroll
            for (int d = 0; d < 4; d++) {
                float lo, hi;
                unpack2(acc[a][d], lo, hi);
                atomicAdd(&S_sh[(ti + a) * NPAD + tj + 2 * d], lo);
                atomicAdd(&S_sh[(ti + a) * NPAD + tj + 2 * d + 1], hi);
            }
    }
    __syncthreads();

    float* sp = SP_glob + (size_t)(b * PP + p) * SSZ;
    for (int idx = tid; idx < SSZ; idx += 256) sp[idx] = S_sh[idx];
}

// ---------------- Kernel R: reduce 8 partials ----------------
__global__ __launch_bounds__(256)
void cam_reduce() {
    const int b = blockIdx.x;
    const int tid = threadIdx.x;
    const float4* sp = (const float4*)(SP_glob + (size_t)b * PP * SSZ);
    float4* sr = (float4*)(S_red + (size_t)b * SSZ);
    for (int idx = tid; idx < SSZ / 4; idx += 256) {
        float4 s = sp[idx];
        #pragma unroll
        for (int pp = 1; pp < PP; pp++) {
            float4 t = sp[pp * (SSZ / 4) + idx];
            s.x += t.x; s.y += t.y; s.z += t.z; s.w += t.w;
        }
        sr[idx] = s;
    }
}

// ---------------- Kernel B: out_slice = q_slice @ S + v_slice ----------------
__global__ __launch_bounds__(256)
void cam_out(const float* __restrict__ q, const float* __restrict__ v,
             float* __restrict__ out) {
    __shared__ __align__(16) float q_sh[CH * NN];   // 25.1 KB (stride 49)
    __shared__ __align__(16) float S_sh[SSZ];       // 10.7 KB (stride 56)

    const int b = blockIdx.x;
    const int p = blockIdx.y;
    const int tid = threadIdx.x;
    const size_t base = ((size_t)b * CC + (size_t)p * CH) * NN;

    // stage reduced S (686 float4)
    const float4* s4 = (const float4*)(S_red + (size_t)b * SSZ);
    for (int idx = tid; idx < SSZ / 4; idx += 256)
        ((float4*)S_sh)[idx] = s4[idx];
    // stage q slice (1568 float4)
    const float4* q4 = (const float4*)(q + base);
    for (int idx = tid; idx < (CH * NN) / 4; idx += 256)
        ((float4*)q_sh)[idx] = q4[idx];
    __syncthreads();

    // 32 channel-groups (4 ch) x 7 col-tiles (8 padded cols) = 224 threads
    const int cg = tid / 7;             // active when cg < 32
    const int jt = (tid % 7) * 8;

    if (cg < 32) {
        const int cbase = cg * 4;
        u64 acc[4][4];
        #pragma unroll
        for (int a = 0; a < 4; a++)
            #pragma unroll
            for (int d = 0; d < 4; d++) acc[a][d] = 0ULL;

        #pragma unroll 7
        for (int i = 0; i < NN; i++) {
            u64 qp[4], sp_[4];
            #pragma unroll
            for (int a = 0; a < 4; a++) {
                float qv = q_sh[(cbase + a) * NN + i];
                qp[a] = pack2(qv, qv);
            }
            #pragma unroll
            for (int d = 0; d < 4; d++)
                sp_[d] = *(const u64*)&S_sh[i * NPAD + jt + 2 * d];
            #pragma unroll
            for (int a = 0; a < 4; a++)
                #pragma unroll
                for (int d = 0; d < 4; d++)
                    acc[a][d] = fma2(qp[a], sp_[d], acc[a][d]);
        }

        const float* vb = v + base;
        float* ob = out + base;
        #pragma unroll
        for (int a = 0; a < 4; a++) {
            const int crow = (cbase + a) * NN;
            #pragma unroll
            for (int d = 0; d < 4; d++) {
                float lo, hi;
                unpack2(acc[a][d], lo, hi);
                int j0 = jt + 2 * d;
                if (j0 < NN)     ob[crow + j0]     = lo + vb[crow + j0];
                if (j0 + 1 < NN) ob[crow + j0 + 1] = hi + vb[crow + j0 + 1];
            }
        }
    }
}

extern "C" void kernel_launch(void* const* d_in, const int* in_sizes, int n_in,
                              void* d_out, int out_size) {
    const float* v1 = (const float*)d_in[0];
    const float* q1 = (const float*)d_in[1];
    const float* k1 = (const float*)d_in[2];
    float* out = (float*)d_out;

    dim3 grid(BB, PP);
    cam_partS<<<grid, 256>>>(k1, v1);
    cam_reduce<<<BB, 256>>>();
    cam_out<<<grid, 256>>>(q1, v1, out);
}

// round 5
// speedup vs baseline: 1.4085x; 1.4085x over previous
#include <cuda_runtime.h>

// CAM: out[b] = (q[b]@k[b]^T)@v[b] + v1  ==  q[b] @ (k[b]^T @ v[b]) + v1
// B=128, C=1024, N=49 (padded to 56). fp32, packed fma.rn.f32x2 math.
//
// A: grid(128,8)  x256thr : 2 groups x 98thr; group partial S (64ch) -> SP_glob
// R: grid(128)    x256thr : sum 16 partials -> S_red
// B: grid(128,16) x256thr : out-slice(64ch) = q_slice @ S + v_slice

#define BB 128
#define CC 1024
#define NN 49
#define NPAD 56
#define SSZ (NN * NPAD)      // 2744
#define PPA 8                // kernel A channel splits (128 ch each)
#define NPART 16             // partials per batch (PPA * 2 groups)
#define PPB 16               // kernel B channel splits (64 ch each)
#define SC 64                // channels staged per chunk

__device__ float SP_glob[BB * NPART * SSZ];   // 22.5 MB partials
__device__ float S_red[BB * SSZ];             // 1.4 MB reduced S

typedef unsigned long long u64;

__device__ __forceinline__ void unpack2(u64 p, float& lo, float& hi) {
    asm("mov.b64 {%0,%1}, %2;" : "=f"(lo), "=f"(hi) : "l"(p));
}
__device__ __forceinline__ u64 fma2(u64 a, u64 b, u64 c) {
    u64 d; asm("fma.rn.f32x2 %0, %1, %2, %3;" : "=l"(d) : "l"(a), "l"(b), "l"(c));
    return d;
}

// ---------------- Kernel A: group partials of S = k^T @ v ----------------
__global__ __launch_bounds__(256)
void cam_partS(const float* __restrict__ k, const float* __restrict__ v) {
    __shared__ __align__(16) float2 k_dup[SC * NN];   // 25.1 KB, (k,k) pairs
    __shared__ __align__(16) float  v_sh[SC * NPAD];  // 14.0 KB, zero-padded cols
    // total 39.1 KB static

    const int b = blockIdx.x;
    const int p = blockIdx.y;
    const int tid = threadIdx.x;
    const int g = tid >> 7;            // group 0/1 (channel split within CTA)
    const int t = tid & 127;           // 0..127, active when t < 98
    const bool active = (t < 98);
    const int ti = (t / 14) * 7;       // S row base (7 tiles)
    const int tj = (t % 14) * 4;       // S col base (14 tiles of 4 cols)

    const size_t base = ((size_t)b * CC + (size_t)p * (2 * SC)) * NN;
    const float* kb = k + base;
    const float* vb = v + base;

    u64 acc[7][2];
    #pragma unroll
    for (int a = 0; a < 7; a++) { acc[a][0] = 0ULL; acc[a][1] = 0ULL; }

    #pragma unroll
    for (int chunk = 0; chunk < 2; chunk++) {
        __syncthreads();
        // stage k duplicated: coalesced read, STS.64 pair write
        const float* ksrc = kb + (size_t)chunk * SC * NN;
        for (int idx = tid; idx < SC * NN; idx += 256) {
            float kv = ksrc[idx];
            k_dup[idx] = make_float2(kv, kv);
        }
        // stage v into padded layout (zero cols 49..55)
        const float* vsrc = vb + (size_t)chunk * SC * NN;
        for (int idx = tid; idx < SC * NPAD; idx += 256) {
            int cc = idx / NPAD, ii = idx - cc * NPAD;
            v_sh[idx] = (ii < NN) ? vsrc[cc * NN + ii] : 0.f;
        }
        __syncthreads();

        if (active) {
            #pragma unroll 4
            for (int cl = 0; cl < 32; cl++) {
                const int cc = g * 32 + cl;
                u64 krp[7], vp[2];
                #pragma unroll
                for (int a = 0; a < 7; a++)
                    krp[a] = *(const u64*)&k_dup[cc * NN + ti + a];
                vp[0] = *(const u64*)&v_sh[cc * NPAD + tj];
                vp[1] = *(const u64*)&v_sh[cc * NPAD + tj + 2];
                #pragma unroll
                for (int a = 0; a < 7; a++) {
                    acc[a][0] = fma2(krp[a], vp[0], acc[a][0]);
                    acc[a][1] = fma2(krp[a], vp[1], acc[a][1]);
                }
            }
        }
    }

    if (active) {
        float* sp = SP_glob + (size_t)((b * PPA + p) * 2 + g) * SSZ;
        #pragma unroll
        for (int a = 0; a < 7; a++) {
            *(u64*)&sp[(ti + a) * NPAD + tj]     = acc[a][0];
            *(u64*)&sp[(ti + a) * NPAD + tj + 2] = acc[a][1];
        }
    }
}

// ---------------- Kernel R: reduce 16 partials ----------------
__global__ __launch_bounds__(256)
void cam_reduce() {
    const int b = blockIdx.x;
    const int tid = threadIdx.x;
    const float4* sp = (const float4*)(SP_glob + (size_t)b * NPART * SSZ);
    float4* sr = (float4*)(S_red + (size_t)b * SSZ);
    for (int idx = tid; idx < SSZ / 4; idx += 256) {
        float4 s = sp[idx];
        #pragma unroll
        for (int pp = 1; pp < NPART; pp++) {
            float4 u = sp[pp * (SSZ / 4) + idx];
            s.x += u.x; s.y += u.y; s.z += u.z; s.w += u.w;
        }
        sr[idx] = s;
    }
}

// ---------------- Kernel B: out_slice = q_slice @ S + v_slice ----------------
__global__ __launch_bounds__(256)
void cam_out(const float* __restrict__ q, const float* __restrict__ v,
             float* __restrict__ out) {
    __shared__ __align__(16) float2 q_dup[SC * NN];   // 25.1 KB (q,q) pairs
    __shared__ __align__(16) float  S_sh[SSZ];        // 10.7 KB padded S
    // total 35.8 KB static

    const int b = blockIdx.x;
    const int p = blockIdx.y;
    const int tid = threadIdx.x;
    const size_t base = ((size_t)b * CC + (size_t)p * SC) * NN;

    // stage reduced S (padded, float4)
    const float4* s4 = (const float4*)(S_red + (size_t)b * SSZ);
    for (int idx = tid; idx < SSZ / 4; idx += 256)
        ((float4*)S_sh)[idx] = s4[idx];
    // stage q duplicated
    const float* qsrc = q + base;
    for (int idx = tid; idx < SC * NN; idx += 256) {
        float qv = qsrc[idx];
        q_dup[idx] = make_float2(qv, qv);
    }
    __syncthreads();

    // 16 channel-groups (4 ch) x 14 col-tiles (4 cols) = 224 active threads
    const bool active = (tid < 224);
    const int cg = tid / 14;
    const int jt = (tid % 14) * 4;

    if (active) {
        const int cbase = cg * 4;
        u64 acc[4][2];
        #pragma unroll
        for (int a = 0; a < 4; a++) { acc[a][0] = 0ULL; acc[a][1] = 0ULL; }

        #pragma unroll 7
        for (int i = 0; i < NN; i++) {
            u64 qp[4], sp0, sp1;
            #pragma unroll
            for (int a = 0; a < 4; a++)
                qp[a] = *(const u64*)&q_dup[(cbase + a) * NN + i];
            sp0 = *(const u64*)&S_sh[i * NPAD + jt];
            sp1 = *(const u64*)&S_sh[i * NPAD + jt + 2];
            #pragma unroll
            for (int a = 0; a < 4; a++) {
                acc[a][0] = fma2(qp[a], sp0, acc[a][0]);
                acc[a][1] = fma2(qp[a], sp1, acc[a][1]);
            }
        }

        const float* vb = v + base;
        float* ob = out + base;
        #pragma unroll
        for (int a = 0; a < 4; a++) {
            const int crow = (cbase + a) * NN;
            #pragma unroll
            for (int d = 0; d < 2; d++) {
                float lo, hi;
                unpack2(acc[a][d], lo, hi);
                int j0 = jt + 2 * d;
                if (j0 < NN)     ob[crow + j0]     = lo + vb[crow + j0];
                if (j0 + 1 < NN) ob[crow + j0 + 1] = hi + vb[crow + j0 + 1];
            }
        }
    }
}

extern "C" void kernel_launch(void* const* d_in, const int* in_sizes, int n_in,
                              void* d_out, int out_size) {
    const float* v1 = (const float*)d_in[0];
    const float* q1 = (const float*)d_in[1];
    const float* k1 = (const float*)d_in[2];
    float* out = (float*)d_out;

    cam_partS<<<dim3(BB, PPA), 256>>>(k1, v1);
    cam_reduce<<<BB, 256>>>();
    cam_out<<<dim3(BB, PPB), 256>>>(q1, v1, out);
}